// round 14
// baseline (speedup 1.0000x reference)
#include <cuda_runtime.h>
#include <math.h>

#define AT 48
#define SP 4
#define RCRf 5.2f
#define RCAf 3.5f
#define NSHFR 16
#define NSHFA 4
#define NSHFZ 8
#define RADSUB (SP * NSHFR)                 // 64
#define ANGSUB (NSHFA * NSHFZ)              // 32
#define NPAIRS_SP (SP * (SP + 1) / 2)       // 10
#define OUTW (RADSUB + NPAIRS_SP * ANGSUB)  // 384
#define WARPS 4
#define NT (WARPS * 32)
#define PI_F 3.14159265358979f

__global__ __launch_bounds__(NT) void aev_kernel(
    const float* __restrict__ coords,   // (M, A, 3)
    const float* __restrict__ gEtaR,
    const float* __restrict__ gShfR,
    const float* __restrict__ gEtaA,
    const float* __restrict__ gZeta,
    const float* __restrict__ gShfA,
    const float* __restrict__ gShfZ,
    const int*   __restrict__ species,  // (M, A)
    float* __restrict__ out)            // (M, A, 384)
{
    const int m    = blockIdx.y;
    const int tid  = threadIdx.x;
    const int wid  = tid >> 5;
    const int lane = tid & 31;
    const int i    = blockIdx.x * WARPS + wid;   // this warp's center atom

    __shared__ float scx[AT], scy[AT], scz[AT];
    __shared__ int   ssp[AT];
    __shared__ float4 nbrA[WARPS][AT];   // {dx, dy, dz, 1/d}
    __shared__ float4 nbrB[WARPS][AT];   // {d, fc_ang, species(bits), pad}
    __shared__ float  dall[WARPS][AT];
    __shared__ float  accA[WARPS][NPAIRS_SP * ANGSUB];

    // ---- block stage: molecule coords + species (only block-wide sync) ----
    if (tid < AT) {
        const float* c = coords + ((size_t)m * AT + tid) * 3;
        scx[tid] = c[0]; scy[tid] = c[1]; scz[tid] = c[2];
        ssp[tid] = species[m * AT + tid];
    }
    __syncthreads();

    // ---- per-lane params (tiny, L1-cached after first block) ----
    const float etaR = gEtaR[0], etaA = gEtaA[0], zeta = gZeta[0];
    const bool  z32  = (zeta == 32.0f);
    const float shR  = gShfR[lane & 15];          // radial shell for this lane
    const float shA  = gShfA[(lane >> 3) & 3];    // angular (a, z) combo
    float szl, czl;
    __sincosf(gShfZ[lane & 7], &szl, &czl);

    const float cix = scx[i], ciy = scy[i], ciz = scz[i];

    // init per-warp angular accumulator (lane-private column)
    #pragma unroll
    for (int q = 0; q < NPAIRS_SP; q++) accA[wid][q * ANGSUB + lane] = 0.0f;

    // ---- warp-private neighbor staging + ballot compaction ----
    int n;
    {
        // batch 1: atom = lane (0..31)
        float dx = scx[lane] - cix;
        float dy = scy[lane] - ciy;
        float dz = scz[lane] - ciz;
        float d  = sqrtf(dx * dx + dy * dy + dz * dz);
        dall[wid][lane] = d;
        bool p1 = (lane != i) && (d <= RCAf);
        unsigned b1 = __ballot_sync(0xffffffffu, p1);
        int cnt1 = __popc(b1);
        if (p1) {
            int pos = __popc(b1 & ((1u << lane) - 1u));
            float rd = 1.0f / fmaxf(d, 1e-8f);
            float fc = 0.5f * __cosf(d * (PI_F / RCAf)) + 0.5f;
            nbrA[wid][pos] = make_float4(dx, dy, dz, rd);
            nbrB[wid][pos] = make_float4(d, fc, __int_as_float(ssp[lane]), 0.0f);
        }
        // batch 2: atom = 32 + lane (lanes 0..15)
        int a2 = 32 + lane;
        float dx2 = 0.f, dy2 = 0.f, dz2 = 0.f, d2 = 1e9f;
        if (lane < 16) {
            dx2 = scx[a2] - cix; dy2 = scy[a2] - ciy; dz2 = scz[a2] - ciz;
            d2  = sqrtf(dx2 * dx2 + dy2 * dy2 + dz2 * dz2);
            dall[wid][a2] = d2;
        }
        bool p2 = (lane < 16) && (a2 != i) && (d2 <= RCAf);
        unsigned b2 = __ballot_sync(0xffffffffu, p2);
        if (p2) {
            int pos = cnt1 + __popc(b2 & ((1u << lane) - 1u));
            float rd = 1.0f / fmaxf(d2, 1e-8f);
            float fc = 0.5f * __cosf(d2 * (PI_F / RCAf)) + 0.5f;
            nbrA[wid][pos] = make_float4(dx2, dy2, dz2, rd);
            nbrB[wid][pos] = make_float4(d2, fc, __int_as_float(ssp[a2]), 0.0f);
        }
        n = cnt1 + __popc(b2);
    }
    __syncwarp();

    // ---- radial: 2 atoms/iteration (half-warps), register accumulators ----
    float accR[SP] = {0.f, 0.f, 0.f, 0.f};
    {
        const int half = lane >> 4;   // 0: even atoms, 1: odd atoms
        #pragma unroll 4
        for (int t = 0; t < AT / 2; t++) {
            int atom = 2 * t + half;
            float d  = dall[wid][atom];
            int spq  = ssp[atom];
            bool ok  = (atom != i) && (d <= RCRf);
            float fc = 0.5f * __cosf(d * (PI_F / RCRf)) + 0.5f;
            float tt = d - shR;
            float v  = ok ? 0.25f * __expf(-etaR * tt * tt) * fc : 0.0f;
            #pragma unroll
            for (int q = 0; q < SP; q++) accR[q] += (spq == q) ? v : 0.0f;
        }
        #pragma unroll
        for (int q = 0; q < SP; q++)
            accR[q] += __shfl_down_sync(0xffffffffu, accR[q], 16);
    }

    // ---- angular: nested pair loop, warp-uniform pair math, lane = (a,z) ----
    for (int jj = 0; jj < n - 1; jj++) {
        float4 aj = nbrA[wid][jj];
        float4 bj = nbrB[wid][jj];
        int spj = __float_as_int(bj.z);
        for (int kk = jj + 1; kk < n; kk++) {
            float4 ak = nbrA[wid][kk];
            float4 bk = nbrB[wid][kk];
            float dot  = aj.x * ak.x + aj.y * ak.y + aj.z * ak.z;
            float cosv = 0.95f * dot * aj.w * ak.w;
            float sinv = sqrtf(fmaxf(1.0f - cosv * cosv, 0.0f));
            float fcj2 = 2.0f * bj.y * bk.y;
            float dm   = 0.5f * (bj.x + bk.x);
            int spk = __float_as_int(bk.z);
            int lo = min(spj, spk), hi = max(spj, spk);
            int pidx = lo * SP - ((lo * (lo - 1)) >> 1) + (hi - lo);

            // per-lane (a, z) term
            float cd   = cosv * czl + sinv * szl;     // cos(theta - ShfZ[z])
            float base = 0.5f + 0.5f * cd;
            float f1;
            if (z32) {
                float x = base;                        // base^32, even power
                x *= x; x *= x; x *= x; x *= x; x *= x;
                f1 = x;
            } else {
                f1 = __powf(fmaxf(base, 0.0f), zeta);
            }
            float tt = dm - shA;
            float term = f1 * fcj2 * __expf(-etaA * tt * tt);

            accA[wid][pidx * ANGSUB + lane] += term;   // lane-private slot
        }
    }
    __syncwarp();

    // ---- write out ----
    float* o = out + ((size_t)m * AT + i) * OUTW;
    if (lane < 16) {
        #pragma unroll
        for (int q = 0; q < SP; q++) o[q * NSHFR + lane] = accR[q];
    }
    #pragma unroll
    for (int q = 0; q < NPAIRS_SP; q++)
        o[RADSUB + q * ANGSUB + lane] = accA[wid][q * ANGSUB + lane];
}

extern "C" void kernel_launch(void* const* d_in, const int* in_sizes, int n_in,
                              void* d_out, int out_size) {
    const float* coords = (const float*)d_in[0];
    const float* EtaR   = (const float*)d_in[1];
    const float* ShfR   = (const float*)d_in[2];
    const float* EtaA   = (const float*)d_in[3];
    const float* Zeta   = (const float*)d_in[4];
    const float* ShfA   = (const float*)d_in[5];
    const float* ShfZ   = (const float*)d_in[6];
    const int*   sp     = (const int*)d_in[7];
    float* out = (float*)d_out;

    const int M = in_sizes[0] / (AT * 3);
    dim3 grid(AT / WARPS, M);
    aev_kernel<<<grid, NT>>>(coords, EtaR, ShfR, EtaA, Zeta, ShfA, ShfZ, sp, out);
}

// round 16
// speedup vs baseline: 1.5884x; 1.5884x over previous
#include <cuda_runtime.h>
#include <math.h>

#define AT 48
#define SP 4
#define RCRf 5.2f
#define RCAf 3.5f
#define NSHFR 16
#define NSHFA 4
#define NSHFZ 8
#define RADSUB (SP * NSHFR)                 // 64
#define ANGSUB (NSHFA * NSHFZ)              // 32
#define NPAIRS_SP (SP * (SP + 1) / 2)       // 10
#define OUTW (RADSUB + NPAIRS_SP * ANGSUB)  // 384
#define WARPS 4
#define NT (WARPS * 32)
#define PI_F 3.14159265358979f

__device__ __forceinline__ void pair_accum(
    float& acc, const float4 aj, const float2 bj,
    const float4 ak, const float2 bk,
    float czl, float szl, float shA, float etaA, float zeta, bool z32)
{
    float dot  = aj.x * ak.x + aj.y * ak.y + aj.z * ak.z;
    float cosv = 0.95f * dot * aj.w * ak.w;
    float sinv = sqrtf(fmaxf(1.0f - cosv * cosv, 0.0f));
    float cd   = cosv * czl + sinv * szl;   // cos(theta - ShfZ[z])
    float base = 0.5f + 0.5f * cd;
    float f1;
    if (z32) {
        float x = base;                      // base^32: even power, no clamp
        x *= x; x *= x; x *= x; x *= x; x *= x;
        f1 = x;
    } else {
        f1 = __powf(fmaxf(base, 0.0f), zeta);
    }
    float dm = 0.5f * (bj.x + bk.x);
    float tt = dm - shA;
    acc = fmaf(f1, 2.0f * bj.y * bk.y * __expf(-etaA * tt * tt), acc);
}

__global__ __launch_bounds__(NT) void aev_kernel(
    const float* __restrict__ coords,   // (M, A, 3)
    const float* __restrict__ gEtaR,
    const float* __restrict__ gShfR,
    const float* __restrict__ gEtaA,
    const float* __restrict__ gZeta,
    const float* __restrict__ gShfA,
    const float* __restrict__ gShfZ,
    const int*   __restrict__ species,  // (M, A)
    float* __restrict__ out)            // (M, A, 384)
{
    const int i    = blockIdx.x;   // center atom
    const int m    = blockIdx.y;   // molecule
    const int tid  = threadIdx.x;
    const int w    = tid >> 5;
    const int lane = tid & 31;

    // warp-private neighbor lists, species-sorted
    __shared__ float4 angA[WARPS][AT];   // {dx, dy, dz, 1/d}
    __shared__ float2 angB[WARPS][AT];   // {d, fc_ang}
    __shared__ float2 radf[WARPS][AT];   // {d, 0.25*fc_rad}
    __shared__ int    goA[WARPS][SP + 1], goR[WARPS][SP + 1];  // group offsets

    // ---- per-lane params (L1/L2-cached broadcast) ----
    const float etaR = gEtaR[0], etaA = gEtaA[0], zeta = gZeta[0];
    const bool  z32  = (zeta == 32.0f);
    const float shR  = gShfR[lane & 15];
    const float shA  = gShfA[(lane >> 3) & 3];
    float szl, czl;
    __sincosf(gShfZ[lane & 7], &szl, &czl);

    // ---- center coord ----
    const float* cc = coords + ((size_t)m * AT + i) * 3;
    const float cix = cc[0], ciy = cc[1], ciz = cc[2];

    // ---- per-warp staging: 2 batches in registers ----
    const int aA = lane, aB = 32 + lane;
    const float* pA = coords + ((size_t)m * AT + aA) * 3;
    float dxA = pA[0] - cix, dyA = pA[1] - ciy, dzA = pA[2] - ciz;
    float dA  = sqrtf(dxA * dxA + dyA * dyA + dzA * dzA);
    int spA   = species[m * AT + aA];
    float dxB = 0.f, dyB = 0.f, dzB = 0.f, dB = 1e9f;
    int spB   = 0;
    if (lane < 16) {
        const float* pB = coords + ((size_t)m * AT + aB) * 3;
        dxB = pB[0] - cix; dyB = pB[1] - ciy; dzB = pB[2] - ciz;
        dB  = sqrtf(dxB * dxB + dyB * dyB + dzB * dzB);
        spB = species[m * AT + aB];
    }
    const bool vAa = (aA != i) && (dA <= RCAf);
    const bool vBa = (lane < 16) && (aB != i) && (dB <= RCAf);
    const bool vAr = (aA != i) && (dA <= RCRf);
    const bool vBr = (lane < 16) && (aB != i) && (dB <= RCRf);

    const float rdA  = 1.0f / fmaxf(dA, 1e-8f);
    const float rdB  = 1.0f / fmaxf(dB, 1e-8f);
    const float fcaA = 0.5f * __cosf(dA * (PI_F / RCAf)) + 0.5f;
    const float fcaB = 0.5f * __cosf(dB * (PI_F / RCAf)) + 0.5f;
    const float fcrA = 0.25f * (0.5f * __cosf(dA * (PI_F / RCRf)) + 0.5f);
    const float fcrB = 0.25f * (0.5f * __cosf(dB * (PI_F / RCRf)) + 0.5f);
    const unsigned lt = (1u << lane) - 1u;

    // ---- species-sorted ballot compaction: angular then radial ----
    int base = 0;
    #pragma unroll
    for (int s = 0; s < SP; s++) {
        unsigned mA = __ballot_sync(0xffffffffu, vAa && spA == s);
        unsigned mB = __ballot_sync(0xffffffffu, vBa && spB == s);
        if (lane == s) goA[w][s] = base;
        if (vAa && spA == s) {
            int pos = base + __popc(mA & lt);
            angA[w][pos] = make_float4(dxA, dyA, dzA, rdA);
            angB[w][pos] = make_float2(dA, fcaA);
        }
        if (vBa && spB == s) {
            int pos = base + __popc(mA) + __popc(mB & lt);
            angA[w][pos] = make_float4(dxB, dyB, dzB, rdB);
            angB[w][pos] = make_float2(dB, fcaB);
        }
        base += __popc(mA) + __popc(mB);
    }
    if (lane == 0) goA[w][SP] = base;

    base = 0;
    #pragma unroll
    for (int s = 0; s < SP; s++) {
        unsigned mA = __ballot_sync(0xffffffffu, vAr && spA == s);
        unsigned mB = __ballot_sync(0xffffffffu, vBr && spB == s);
        if (lane == s) goR[w][s] = base;
        if (vAr && spA == s) {
            int pos = base + __popc(mA & lt);
            radf[w][pos] = make_float2(dA, fcrA);
        }
        if (vBr && spB == s) {
            int pos = base + __popc(mA) + __popc(mB & lt);
            radf[w][pos] = make_float2(dB, fcrB);
        }
        base += __popc(mA) + __popc(mB);
    }
    if (lane == 0) goR[w][SP] = base;
    __syncwarp();

    // ---- unit loop: warp w owns units w, w+4, w+8 (0-1 radial, 2-11 angular) ----
    float* o = out + ((size_t)m * AT + i) * OUTW;

    #pragma unroll
    for (int ui = 0; ui < 3; ui++) {
        const int u = w + WARPS * ui;
        float acc = 0.0f;
        if (u < 2) {
            // radial: lane = (species, shell); species = 2u + (lane>>4)
            const int sp  = 2 * u + (lane >> 4);
            const int off = goR[w][sp];
            const int cnt = goR[w][sp + 1] - off;
            const int c0  = __shfl_sync(0xffffffffu, cnt, 0);
            const int c1  = __shfl_sync(0xffffffffu, cnt, 16);
            const int mx  = max(c0, c1);
            for (int t = 0; t < mx; t++) {
                if (t < cnt) {
                    float2 v = radf[w][off + t];
                    float tt = v.x - shR;
                    acc = fmaf(v.y, __expf(-etaR * tt * tt), acc);
                }
            }
            o[sp * NSHFR + (lane & 15)] = acc;
        } else {
            // angular bucket b -> species pair (lo, hi)
            const int b  = u - 2;
            const int lo = (b >= 9) ? 3 : ((b >= 7) ? 2 : ((b >= 4) ? 1 : 0));
            const int hi = b - (lo * SP - ((lo * (lo - 1)) >> 1)) + lo;
            const int ja0 = goA[w][lo], ca = goA[w][lo + 1] - ja0;
            const int jb0 = goA[w][hi], cb = goA[w][hi + 1] - jb0;
            if (lo == hi) {
                for (int jj = 0; jj < ca - 1; jj++) {
                    float4 aj = angA[w][ja0 + jj];
                    float2 bj = angB[w][ja0 + jj];
                    for (int kk = jj + 1; kk < ca; kk++) {
                        pair_accum(acc, aj, bj, angA[w][ja0 + kk], angB[w][ja0 + kk],
                                   czl, szl, shA, etaA, zeta, z32);
                    }
                }
            } else {
                for (int jj = 0; jj < ca; jj++) {
                    float4 aj = angA[w][ja0 + jj];
                    float2 bj = angB[w][ja0 + jj];
                    for (int kk = 0; kk < cb; kk++) {
                        pair_accum(acc, aj, bj, angA[w][jb0 + kk], angB[w][jb0 + kk],
                                   czl, szl, shA, etaA, zeta, z32);
                    }
                }
            }
            o[RADSUB + b * ANGSUB + lane] = acc;
        }
    }
}

extern "C" void kernel_launch(void* const* d_in, const int* in_sizes, int n_in,
                              void* d_out, int out_size) {
    const float* coords = (const float*)d_in[0];
    const float* EtaR   = (const float*)d_in[1];
    const float* ShfR   = (const float*)d_in[2];
    const float* EtaA   = (const float*)d_in[3];
    const float* Zeta   = (const float*)d_in[4];
    const float* ShfA   = (const float*)d_in[5];
    const float* ShfZ   = (const float*)d_in[6];
    const int*   sp     = (const int*)d_in[7];
    float* out = (float*)d_out;

    const int M = in_sizes[0] / (AT * 3);
    dim3 grid(AT, M);
    aev_kernel<<<grid, NT>>>(coords, EtaR, ShfR, EtaA, Zeta, ShfA, ShfZ, sp, out);
}